// round 11
// baseline (speedup 1.0000x reference)
#include <cuda_runtime.h>
#include <cuda_bf16.h>
#include <cstdint>

#define FAN 10
constexpr int IN_DIM = 128;
constexpr int HID    = 256;
constexpr int Bsz    = 4096;
constexpr int N2n    = 3 * Bsz;       // 12288
constexpr int N1n    = N2n * FAN;     // 122880
constexpr int ZROWS  = 2 * Bsz;       // 8192

// ---------------- scratch (device globals: allocation-free) ----------------
__device__ __align__(16) float         g_h0 [(size_t)N1n * HID];
__device__ __align__(16) __nv_bfloat16 g_u1h[(size_t)N2n * 2 * HID];
__device__ __align__(16) __nv_bfloat16 g_u1l[(size_t)N2n * 2 * HID];
__device__ __align__(16) float         g_h2 [(size_t)N2n * HID];
__device__ __align__(16) __nv_bfloat16 g_zh [(size_t)ZROWS * HID];
__device__ __align__(16) __nv_bfloat16 g_zl [(size_t)ZROWS * HID];
__device__ __align__(16) __nv_bfloat16 g_z1h[(size_t)ZROWS * HID];
__device__ __align__(16) __nv_bfloat16 g_z1l[(size_t)ZROWS * HID];
__device__ __align__(16) float         g_z2 [(size_t)ZROWS * HID];
// transposed bf16 hi/lo weights: [N=256, K]
__device__ __align__(16) __nv_bfloat16 g_W0h[HID * HID],     g_W0l[HID * HID];
__device__ __align__(16) __nv_bfloat16 g_W1h[HID * 2 * HID], g_W1l[HID * 2 * HID];
__device__ __align__(16) __nv_bfloat16 g_P1h[HID * HID],     g_P1l[HID * HID];
__device__ __align__(16) __nv_bfloat16 g_P2h[HID * HID],     g_P2l[HID * HID];
// row compaction (g_flags zero-init BSS; marks idempotent with fixed inputs)
__device__ int g_cnt;
__device__ int g_flags[N1n];
__device__ int g_newid[N1n];
__device__ int g_orig [N1n];

// ---------------- PTX helpers ----------------
__device__ __forceinline__ uint32_t smem_u32(const void* p) {
    uint32_t a;
    asm("{ .reg .u64 t; cvta.to.shared.u64 t, %1; cvt.u32.u64 %0, t; }" : "=r"(a) : "l"(p));
    return a;
}
__device__ __forceinline__ void mma16816(float* d, const uint32_t* a, const uint32_t* b) {
    asm volatile("mma.sync.aligned.m16n8k16.row.col.f32.bf16.bf16.f32 "
                 "{%0,%1,%2,%3}, {%4,%5,%6,%7}, {%8,%9}, {%0,%1,%2,%3};"
                 : "+f"(d[0]), "+f"(d[1]), "+f"(d[2]), "+f"(d[3])
                 : "r"(a[0]), "r"(a[1]), "r"(a[2]), "r"(a[3]), "r"(b[0]), "r"(b[1]));
}
__device__ __forceinline__ void ldsm4(uint32_t* r, uint32_t addr) {
    asm volatile("ldmatrix.sync.aligned.m8n8.x4.shared.b16 {%0,%1,%2,%3}, [%4];"
                 : "=r"(r[0]), "=r"(r[1]), "=r"(r[2]), "=r"(r[3]) : "r"(addr));
}
#define CP16(dst, src) asm volatile("cp.async.cg.shared.global [%0], [%1], 16;" :: "r"(dst), "l"(src))
#define CP_COMMIT()    asm volatile("cp.async.commit_group;" ::: "memory")
#define CP_WAIT1()     asm volatile("cp.async.wait_group 1;" ::: "memory")
#define CP_WAIT0()     asm volatile("cp.async.wait_group 0;" ::: "memory")

// ---------------- bf16 hi/lo split helpers ----------------
__device__ __forceinline__ __nv_bfloat16 bf_hi(float v) { return __float2bfloat16_rn(v); }
__device__ __forceinline__ void split_store4(__nv_bfloat16* ph, __nv_bfloat16* pl, float4 v) {
    __nv_bfloat16 hx = bf_hi(v.x), hy = bf_hi(v.y), hz = bf_hi(v.z), hw = bf_hi(v.w);
    __nv_bfloat162 h01, h23, l01, l23;
    h01.x = hx; h01.y = hy; h23.x = hz; h23.y = hw;
    l01.x = bf_hi(v.x - __bfloat162float(hx)); l01.y = bf_hi(v.y - __bfloat162float(hy));
    l23.x = bf_hi(v.z - __bfloat162float(hz)); l23.y = bf_hi(v.w - __bfloat162float(hw));
    uint2 H, L;
    H.x = *(unsigned*)&h01; H.y = *(unsigned*)&h23;
    L.x = *(unsigned*)&l01; L.y = *(unsigned*)&l23;
    *(uint2*)ph = H; *(uint2*)pl = L;
}
__device__ __forceinline__ void split_store2(__nv_bfloat16* ph, __nv_bfloat16* pl, float2 v) {
    __nv_bfloat16 hx = bf_hi(v.x), hy = bf_hi(v.y);
    __nv_bfloat162 h, l;
    h.x = hx; h.y = hy;
    l.x = bf_hi(v.x - __bfloat162float(hx)); l.y = bf_hi(v.y - __bfloat162float(hy));
    *(unsigned*)ph = *(unsigned*)&h;
    *(unsigned*)pl = *(unsigned*)&l;
}

// ---------------- weight packing (transposed bf16 hi/lo) + cnt reset ----------------
__global__ void pack_weights(const float* __restrict__ Ws0, const float* __restrict__ Wn0,
                             const float* __restrict__ Ws1, const float* __restrict__ Wn1,
                             const float* __restrict__ Wp1, const float* __restrict__ Wp2) {
    int n = blockIdx.x, k = threadIdx.x;   // 256 x 256
    if (n == 0 && k == 0) g_cnt = 0;
    auto split1 = [](float v, __nv_bfloat16* h, __nv_bfloat16* l) {
        __nv_bfloat16 hb = __float2bfloat16_rn(v);
        *h = hb; *l = __float2bfloat16_rn(v - __bfloat162float(hb));
    };
    float w0 = (k < IN_DIM) ? Ws0[k * HID + n] : Wn0[(k - IN_DIM) * HID + n];
    split1(w0, &g_W0h[n * HID + k], &g_W0l[n * HID + k]);
    split1(Wp1[k * HID + n], &g_P1h[n * HID + k], &g_P1l[n * HID + k]);
    split1(Wp2[k * HID + n], &g_P2h[n * HID + k], &g_P2l[n * HID + k]);
    split1(Ws1[k * HID + n], &g_W1h[n * 2 * HID + k],       &g_W1l[n * 2 * HID + k]);
    split1(Wn1[k * HID + n], &g_W1h[n * 2 * HID + k + HID], &g_W1l[n * 2 * HID + k + HID]);
}

__global__ void mark_rows(const int* __restrict__ nidx1) {
    int e = blockIdx.x * blockDim.x + threadIdx.x;          // 480 x 256
    g_flags[nidx1[e]] = 1;
}

__global__ void compact_rows() {
    int i = blockIdx.x * blockDim.x + threadIdx.x;          // 480 x 256
    int lane = threadIdx.x & 31;
    int f = (i < N2n) || g_flags[i];
    unsigned m = __ballot_sync(0xffffffffu, f);
    int base = 0;
    if (lane == 0 && m) base = atomicAdd(&g_cnt, __popc(m));
    base = __shfl_sync(0xffffffffu, base, 0);
    if (f) {
        int p = base + __popc(m & ((1u << lane) - 1u));
        g_orig[p] = i;
        g_newid[i] = p;
    }
}

// ---------------- fused layer-0: gather+mean -> smem -> HMMA -> h0 ----------------
// Per CTA: 64 compacted rows, full N=256. A tile lives only in smem (no u0
// round-trip). B (weights) streamed via 3-stage cp.async ring, prologue issued
// before the gather so B latency hides behind the random gather.
// smem: A hi[32K] lo[32K] | B 3 stages x (hi 8K + lo 8K) = 114688 B.
// A layout: 16 kc tiles (16 cols each) of [64 rows x 2 chunks(16B)], pitch 32B,
// 4-row-group XOR swizzle -> ldmatrix conflict-free.
constexpr int F0_SMEM = 65536 + 3 * 16384;

__device__ __forceinline__ uint32_t sw_off(int r, int c) {
    return (uint32_t)(((r >> 2) << 7) + (((r & 3) + ((c ^ ((r >> 2) & 1)) << 2)) << 4));
}

__global__ void __launch_bounds__(256, 2) fused0(
    const float* __restrict__ nf, const int* __restrict__ gids,
    const int* __restrict__ nidx,
    const __nv_bfloat16* __restrict__ Bh, const __nv_bfloat16* __restrict__ Bl,
    const float* __restrict__ bias, float* __restrict__ Cf)
{
    extern __shared__ char sm[];
    const int bm = blockIdx.x * 64;
    const int cnt = __ldg(&g_cnt);
    if (bm >= cnt) return;
    const uint32_t sb = smem_u32(sm);
    const int tid = threadIdx.x, lane = tid & 31, wid = tid >> 5;

    auto loadB = [&](int stage, int kc) {
        #pragma unroll
        for (int i = 0; i < 4; i++) {
            int q = tid + i * 256;                  // 1024 16B chunks per stage
            int row = q >> 2, hl = (q >> 1) & 1, ch = q & 1;
            uint32_t dst = sb + 65536 + stage * 16384 + hl * 8192 + sw_off(row, ch);
            const __nv_bfloat16* src = (hl ? Bl : Bh) + (size_t)row * 256 + kc * 16 + ch * 8;
            CP16(dst, src);
        }
    };
    // B prologue (independent of gather)
    loadB(0, 0); CP_COMMIT();
    loadB(1, 1); CP_COMMIT();

    // ---- gather phase: warp handles rows wid*8 .. wid*8+7 ----
    #pragma unroll 1
    for (int rr = 0; rr < 8; rr++) {
        int rl = wid * 8 + rr;
        int gw = bm + rl;
        if (gw >= cnt) break;                       // uniform per warp
        int row = __ldg(&g_orig[gw]);

        int idx_l = 0;
        if (lane < FAN)       idx_l = gids[nidx[(size_t)row * FAN + lane]];
        else if (lane == FAN) idx_l = gids[row];

        int gs = __shfl_sync(0xffffffffu, idx_l, FAN);
        float4 s = __ldg((const float4*)nf + (size_t)gs * (IN_DIM / 4) + lane);

        float4 aa = make_float4(0.f, 0.f, 0.f, 0.f), ab = aa;
        #pragma unroll
        for (int k = 0; k < FAN; k += 2) {
            int ga = __shfl_sync(0xffffffffu, idx_l, k);
            int gb = __shfl_sync(0xffffffffu, idx_l, k + 1);
            float4 va = __ldg((const float4*)nf + (size_t)ga * (IN_DIM / 4) + lane);
            float4 vb = __ldg((const float4*)nf + (size_t)gb * (IN_DIM / 4) + lane);
            aa.x += va.x; aa.y += va.y; aa.z += va.z; aa.w += va.w;
            ab.x += vb.x; ab.y += vb.y; ab.z += vb.z; ab.w += vb.w;
        }
        const float inv = 1.0f / FAN;
        float4 a = make_float4((aa.x + ab.x) * inv, (aa.y + ab.y) * inv,
                               (aa.z + ab.z) * inv, (aa.w + ab.w) * inv);

        // store: lane covers cols 4l..4l+3 (self) and 128+4l.. (agg)
        int kcs = lane >> 2;
        int c   = (lane >> 1) & 1;
        int bo  = (lane & 1) * 8;
        uint32_t off_s = (uint32_t)(kcs * 2048)       + sw_off(rl, c) + bo;
        uint32_t off_a = (uint32_t)((8 + kcs) * 2048) + sw_off(rl, c) + bo;
        split_store4((__nv_bfloat16*)(sm + off_s), (__nv_bfloat16*)(sm + 32768 + off_s), s);
        split_store4((__nv_bfloat16*)(sm + off_a), (__nv_bfloat16*)(sm + 32768 + off_a), a);
    }
    __syncthreads();   // A visible to all; also anchors the B pipeline

    // ---- GEMM phase: 8 warps 1m x 8n, warp tile 64x32, K=256 as 16 k16 steps ----
    float acc[4][4][4];
    #pragma unroll
    for (int i = 0; i < 4; i++)
        #pragma unroll
        for (int j = 0; j < 4; j++)
            #pragma unroll
            for (int k = 0; k < 4; k++) acc[i][j][k] = 0.f;

    const int wn = wid * 32;
    for (int kc = 0; kc < 16; kc++) {
        if (kc == 15) { CP_WAIT0(); } else { CP_WAIT1(); }
        __syncthreads();
        const uint32_t bbase = sb + 65536 + (kc % 3) * 16384;

        uint32_t aR[4][4], bH[2][4], bL[2][4];
        #pragma unroll
        for (int p = 0; p < 2; p++) {
            int row = wn + p * 16 + (lane & 7) + ((lane >> 4) << 3);
            int bc  = (lane >> 3) & 1;
            uint32_t so = sw_off(row, bc);
            ldsm4(bH[p], bbase + so);
            ldsm4(bL[p], bbase + 8192 + so);
        }
        const int arow = lane & 15, ac = lane >> 4;
        #pragma unroll
        for (int mt = 0; mt < 4; mt++)
            ldsm4(aR[mt], sb + kc * 2048 + sw_off(arow + mt * 16, ac));
        // pass 1: Ah * Bh
        #pragma unroll
        for (int mt = 0; mt < 4; mt++)
            #pragma unroll
            for (int nt = 0; nt < 4; nt++)
                mma16816(acc[mt][nt], aR[mt], &bH[nt >> 1][(nt & 1) * 2]);
        // pass 2: Ah * Bl
        #pragma unroll
        for (int mt = 0; mt < 4; mt++)
            #pragma unroll
            for (int nt = 0; nt < 4; nt++)
                mma16816(acc[mt][nt], aR[mt], &bL[nt >> 1][(nt & 1) * 2]);
        // reload A with lo, pass 3: Al * Bh
        #pragma unroll
        for (int mt = 0; mt < 4; mt++)
            ldsm4(aR[mt], sb + 32768 + kc * 2048 + sw_off(arow + mt * 16, ac));
        #pragma unroll
        for (int mt = 0; mt < 4; mt++)
            #pragma unroll
            for (int nt = 0; nt < 4; nt++)
                mma16816(acc[mt][nt], aR[mt], &bH[nt >> 1][(nt & 1) * 2]);

        if (kc + 2 < 16) { loadB((kc + 2) % 3, kc + 2); CP_COMMIT(); }
    }

    // ---- epilogue: bias + relu, coalesced float2 stores into h0 (compacted rows) ----
    const int tg = lane >> 2, tt = lane & 3;
    #pragma unroll
    for (int nt = 0; nt < 4; nt++) {
        int col = wn + nt * 8 + 2 * tt;
        float2 b2 = *(const float2*)(bias + col);
        #pragma unroll
        for (int mt = 0; mt < 4; mt++) {
            int r0 = bm + mt * 16 + tg;
            float2 v0, v1;
            v0.x = fmaxf(acc[mt][nt][0] + b2.x, 0.f); v0.y = fmaxf(acc[mt][nt][1] + b2.y, 0.f);
            v1.x = fmaxf(acc[mt][nt][2] + b2.x, 0.f); v1.y = fmaxf(acc[mt][nt][3] + b2.y, 0.f);
            *(float2*)(Cf + (size_t)r0 * 256 + col)       = v0;
            *(float2*)(Cf + (size_t)(r0 + 8) * 256 + col) = v1;
        }
    }
}

// ---------------- layer1 gather + mean over compacted g_h0 -> bf16 hi/lo ----------------
__global__ void gather_agg1(const int* __restrict__ nidx) {
    int gw   = (blockIdx.x * blockDim.x + threadIdx.x) >> 5;
    int lane = threadIdx.x & 31;

    int idx_l = 0;
    if (lane < FAN)       idx_l = __ldg(&g_newid[nidx[(size_t)gw * FAN + lane]]);
    else if (lane == FAN) idx_l = __ldg(&g_newid[gw]);

    float4 a0 = make_float4(0.f, 0.f, 0.f, 0.f), a1 = a0;
    #pragma unroll
    for (int k = 0; k < FAN; k++) {
        int j = __shfl_sync(0xffffffffu, idx_l, k);
        const float4* row = (const float4*)g_h0 + (size_t)j * (HID / 4);
        float4 v0 = __ldg(row + lane);
        float4 v1 = __ldg(row + 32 + lane);
        a0.x += v0.x; a0.y += v0.y; a0.z += v0.z; a0.w += v0.w;
        a1.x += v1.x; a1.y += v1.y; a1.z += v1.z; a1.w += v1.w;
    }
    int js = __shfl_sync(0xffffffffu, idx_l, FAN);
    const float4* srow = (const float4*)g_h0 + (size_t)js * (HID / 4);
    float4 s0 = __ldg(srow + lane), s1 = __ldg(srow + 32 + lane);

    const float inv = 1.0f / FAN;
    a0.x *= inv; a0.y *= inv; a0.z *= inv; a0.w *= inv;
    a1.x *= inv; a1.y *= inv; a1.z *= inv; a1.w *= inv;

    size_t rb = (size_t)gw * (2 * HID);
    split_store4(g_u1h + rb + 4 * lane,       g_u1l + rb + 4 * lane,       s0);
    split_store4(g_u1h + rb + 128 + 4 * lane, g_u1l + rb + 128 + 4 * lane, s1);
    split_store4(g_u1h + rb + 256 + 4 * lane, g_u1l + rb + 256 + 4 * lane, a0);
    split_store4(g_u1h + rb + 384 + 4 * lane, g_u1l + rb + 384 + 4 * lane, a1);
}

// ---------------- HMMA GEMM (GEMM2 + MLP): unchanged from R10 ----------------
constexpr int GEMM_SMEM = 65536;

template <bool RELU, bool SPLIT>
__global__ void __launch_bounds__(256, 2) hgemm(
    const __nv_bfloat16* __restrict__ Ah, const __nv_bfloat16* __restrict__ Al,
    const __nv_bfloat16* __restrict__ Bh, const __nv_bfloat16* __restrict__ Bl,
    const float* __restrict__ bias,
    float* __restrict__ Cf, __nv_bfloat16* __restrict__ Ch, __nv_bfloat16* __restrict__ Cl,
    int K, const int* Mlim)
{
    extern __shared__ char sm[];
    const int bm = blockIdx.y * 128, bn = blockIdx.x * 128;
    if (Mlim != nullptr && bm >= __ldg(Mlim)) return;
    const uint32_t sb = smem_u32(sm);
    const int tid = threadIdx.x, lane = tid & 31, wid = tid >> 5;
    const int wm = (wid >> 2) * 64, wn = (wid & 3) * 32;
    const int nCh = K >> 5;

    auto swo = [](int r, int c) -> uint32_t { return (uint32_t)(r * 64 + ((c ^ ((r >> 1) & 3)) << 4)); };

    auto load_stage = [&](int stage, int kc) {
        const uint32_t base = sb + stage * 32768;
        #pragma unroll
        for (int i = 0; i < 2; i++) {
            int q = tid + i * 256;
            int r = q >> 2, c = q & 3;
            uint32_t so = swo(r, c);
            size_t ga = (size_t)(bm + r) * K + kc * 32 + c * 8;
            size_t gb = (size_t)(bn + r) * K + kc * 32 + c * 8;
            CP16(base +         so, Ah + ga);
            CP16(base +  8192 + so, Al + ga);
            CP16(base + 16384 + so, Bh + gb);
            CP16(base + 24576 + so, Bl + gb);
        }
    };

    float acc[4][4][4];
    #pragma unroll
    for (int i = 0; i < 4; i++)
        #pragma unroll
        for (int j = 0; j < 4; j++)
            #pragma unroll
            for (int k = 0; k < 4; k++) acc[i][j][k] = 0.f;

    load_stage(0, 0);
    CP_COMMIT();

    for (int kc = 0; kc < nCh; kc++) {
        if (kc + 1 < nCh) { load_stage((kc + 1) & 1, kc + 1); CP_COMMIT(); CP_WAIT1(); }
        else              { CP_WAIT0(); }
        __syncthreads();

        const uint32_t base = sb + (kc & 1) * 32768;
        #pragma unroll
        for (int ks = 0; ks < 2; ks++) {
            uint32_t aR[4][4], bH[2][4], bL[2][4];
            const int akch = 2 * ks + (lane >> 4);
            const int arow = wm + (lane & 15);
            #pragma unroll
            for (int p = 0; p < 2; p++) {
                int row = wn + p * 16 + (lane & 7) + ((lane >> 4) << 3);
                int kch = 2 * ks + ((lane >> 3) & 1);
                uint32_t so = swo(row, kch);
                ldsm4(bH[p], base + 16384 + so);
                ldsm4(bL[p], base + 24576 + so);
            }
            #pragma unroll
            for (int mt = 0; mt < 4; mt++)
                ldsm4(aR[mt], base + swo(arow + mt * 16, akch));
            #pragma unroll
            for (int mt = 0; mt < 4; mt++)
                #pragma unroll
                for (int nt = 0; nt < 4; nt++)
                    mma16816(acc[mt][nt], aR[mt], &bH[nt >> 1][(nt & 1) * 2]);
            #pragma unroll
            for (int mt = 0; mt < 4; mt++)
                #pragma unroll
                for (int nt = 0; nt < 4; nt++)
                    mma16816(acc[mt][nt], aR[mt], &bL[nt >> 1][(nt & 1) * 2]);
            #pragma unroll
            for (int mt = 0; mt < 4; mt++)
                ldsm4(aR[mt], base + 8192 + swo(arow + mt * 16, akch));
            #pragma unroll
            for (int mt = 0; mt < 4; mt++)
                #pragma unroll
                for (int nt = 0; nt < 4; nt++)
                    mma16816(acc[mt][nt], aR[mt], &bH[nt >> 1][(nt & 1) * 2]);
        }
        __syncthreads();
    }

    const int tg = lane >> 2, tt = lane & 3;
    #pragma unroll
    for (int nt = 0; nt < 4; nt++) {
        int col = bn + wn + nt * 8 + 2 * tt;
        float2 b2 = *(const float2*)(bias + col);
        #pragma unroll
        for (int mt = 0; mt < 4; mt++) {
            int r0 = bm + wm + mt * 16 + tg;
            float2 v0, v1;
            v0.x = acc[mt][nt][0] + b2.x; v0.y = acc[mt][nt][1] + b2.y;
            v1.x = acc[mt][nt][2] + b2.x; v1.y = acc[mt][nt][3] + b2.y;
            if (RELU) {
                v0.x = fmaxf(v0.x, 0.f); v0.y = fmaxf(v0.y, 0.f);
                v1.x = fmaxf(v1.x, 0.f); v1.y = fmaxf(v1.y, 0.f);
            }
            size_t o0 = (size_t)r0 * 256 + col, o1 = o0 + 8 * 256;
            if (!SPLIT) {
                *(float2*)(Cf + o0) = v0;
                *(float2*)(Cf + o1) = v1;
            } else {
                split_store2(Ch + o0, Cl + o0, v0);
                split_store2(Ch + o1, Cl + o1, v1);
            }
        }
    }
}

// ---------------- z[r] = h2[r mod B] * h2[B + r], split to bf16 hi/lo ----------------
__global__ void build_z() {
    int r = blockIdx.x, c = threadIdx.x;
    const float4* s = (const float4*)(g_h2 + (size_t)(r & (Bsz - 1)) * HID);
    const float4* o = (const float4*)(g_h2 + (size_t)(Bsz + r) * HID);
    float4 a = s[c], b = o[c];
    float4 v = make_float4(a.x * b.x, a.y * b.y, a.z * b.z, a.w * b.w);
    split_store4(g_zh + (size_t)r * HID + 4 * c, g_zl + (size_t)r * HID + 4 * c, v);
}

// ---------------- scores = z2 @ Wp3 + bp3 ----------------
__global__ void final_dot(const float* __restrict__ Wp3, const float* __restrict__ bp3,
                          float* __restrict__ out) {
    int gw   = (blockIdx.x * blockDim.x + threadIdx.x) >> 5;
    int lane = threadIdx.x & 31;
    const float4* z = (const float4*)(g_z2 + (size_t)gw * HID);
    const float4* w = (const float4*)Wp3;
    float4 z0 = z[lane], z1 = z[32 + lane];
    float4 w0 = __ldg(w + lane), w1 = __ldg(w + 32 + lane);
    float s = z0.x * w0.x + z0.y * w0.y + z0.z * w0.z + z0.w * w0.w
            + z1.x * w1.x + z1.y * w1.y + z1.z * w1.z + z1.w * w1.w;
    #pragma unroll
    for (int o = 16; o; o >>= 1) s += __shfl_xor_sync(0xffffffffu, s, o);
    if (lane == 0) out[gw] = s + bp3[0];
}

extern "C" void kernel_launch(void* const* d_in, const int* in_sizes, int n_in,
                              void* d_out, int out_size) {
    const float* node_feat = (const float*)d_in[0];
    const int*   gids0     = (const int*)d_in[1];
    const int*   nidx0     = (const int*)d_in[2];
    const int*   nidx1     = (const int*)d_in[3];
    const float* Ws0 = (const float*)d_in[4];
    const float* Wn0 = (const float*)d_in[5];
    const float* b0  = (const float*)d_in[6];
    const float* Ws1 = (const float*)d_in[7];
    const float* Wn1 = (const float*)d_in[8];
    const float* b1  = (const float*)d_in[9];
    const float* Wp1 = (const float*)d_in[10];
    const float* bp1 = (const float*)d_in[11];
    const float* Wp2 = (const float*)d_in[12];
    const float* bp2 = (const float*)d_in[13];
    const float* Wp3 = (const float*)d_in[14];
    const float* bp3 = (const float*)d_in[15];
    float* out = (float*)d_out;

    cudaFuncSetAttribute(fused0, cudaFuncAttributeMaxDynamicSharedMemorySize, F0_SMEM);
    cudaFuncSetAttribute(hgemm<false, false>, cudaFuncAttributeMaxDynamicSharedMemorySize, GEMM_SMEM);
    cudaFuncSetAttribute(hgemm<true,  true >, cudaFuncAttributeMaxDynamicSharedMemorySize, GEMM_SMEM);
    cudaFuncSetAttribute(hgemm<true,  false>, cudaFuncAttributeMaxDynamicSharedMemorySize, GEMM_SMEM);

    __nv_bfloat16 *u1h, *u1l, *zh, *zl, *z1h, *z1l;
    __nv_bfloat16 *W0h, *W0l, *W1h, *W1l, *P1h, *P1l, *P2h, *P2l;
    float *h0, *h2, *z2;
    cudaGetSymbolAddress((void**)&u1h, g_u1h); cudaGetSymbolAddress((void**)&u1l, g_u1l);
    cudaGetSymbolAddress((void**)&zh,  g_zh);  cudaGetSymbolAddress((void**)&zl,  g_zl);
    cudaGetSymbolAddress((void**)&z1h, g_z1h); cudaGetSymbolAddress((void**)&z1l, g_z1l);
    cudaGetSymbolAddress((void**)&W0h, g_W0h); cudaGetSymbolAddress((void**)&W0l, g_W0l);
    cudaGetSymbolAddress((void**)&W1h, g_W1h); cudaGetSymbolAddress((void**)&W1l, g_W1l);
    cudaGetSymbolAddress((void**)&P1h, g_P1h); cudaGetSymbolAddress((void**)&P1l, g_P1l);
    cudaGetSymbolAddress((void**)&P2h, g_P2h); cudaGetSymbolAddress((void**)&P2l, g_P2l);
    cudaGetSymbolAddress((void**)&h0,  g_h0);  cudaGetSymbolAddress((void**)&h2,  g_h2);
    cudaGetSymbolAddress((void**)&z2,  g_z2);

    // (1) pack weights + reset counter
    pack_weights<<<HID, HID>>>(Ws0, Wn0, Ws1, Wn1, Wp1, Wp2);
    // (2) mark live rows
    mark_rows<<<(N2n * FAN) / 256, 256>>>(nidx1);
    // (3) compact live rows
    compact_rows<<<N1n / 256, 256>>>();
    // (4) fused layer-0 gather + GEMM — profiled launch
    fused0<<<N1n / 64, 256, F0_SMEM>>>(node_feat, gids0, nidx0, W0h, W0l, b0, h0);

    // layer 1
    gather_agg1<<<N2n / 8, 256>>>(nidx1);
    hgemm<false, false><<<dim3(2, N2n / 128), 256, GEMM_SMEM>>>(
        u1h, u1l, W1h, W1l, b1, h2, nullptr, nullptr, 2 * HID, nullptr);

    // edge MLP
    build_z<<<ZROWS, 64>>>();
    hgemm<true, true><<<dim3(2, ZROWS / 128), 256, GEMM_SMEM>>>(
        zh, zl, P1h, P1l, bp1, nullptr, z1h, z1l, HID, nullptr);
    hgemm<true, false><<<dim3(2, ZROWS / 128), 256, GEMM_SMEM>>>(
        z1h, z1l, P2h, P2l, bp2, z2, nullptr, nullptr, HID, nullptr);
    final_dot<<<ZROWS / 8, 256>>>(Wp3, bp3, out);
}

// round 13
// speedup vs baseline: 1.5535x; 1.5535x over previous
#include <cuda_runtime.h>
#include <cuda_fp16.h>
#include <cstdint>

#define FAN 10
constexpr int IN_DIM = 128;
constexpr int HID    = 256;
constexpr int Bsz    = 4096;
constexpr int N2n    = 3 * Bsz;       // 12288
constexpr int N1n    = N2n * FAN;     // 122880
constexpr int ZROWS  = 2 * Bsz;       // 8192

// ---------------- scratch (device globals: allocation-free) ----------------
__device__ __align__(16) __half g_u0[(size_t)N1n * HID];          // activations, single fp16
__device__ __align__(16) float  g_h0[(size_t)N1n * HID];
__device__ __align__(16) __half g_u1[(size_t)N2n * 2 * HID];
__device__ __align__(16) float  g_h2[(size_t)N2n * HID];
__device__ __align__(16) __half g_zq [(size_t)ZROWS * HID];
__device__ __align__(16) __half g_z1q[(size_t)ZROWS * HID];
__device__ __align__(16) float  g_z2 [(size_t)ZROWS * HID];
// transposed fp16 hi/lo weights: [N=256, K]
__device__ __align__(16) __half g_W0h[HID * HID],     g_W0l[HID * HID];
__device__ __align__(16) __half g_W1h[HID * 2 * HID], g_W1l[HID * 2 * HID];
__device__ __align__(16) __half g_P1h[HID * HID],     g_P1l[HID * HID];
__device__ __align__(16) __half g_P2h[HID * HID],     g_P2l[HID * HID];
// row compaction (g_flags zero-init BSS; marks idempotent with fixed inputs)
__device__ int g_cnt;
__device__ int g_flags[N1n];
__device__ int g_newid[N1n];
__device__ int g_orig [N1n];

// ---------------- PTX helpers ----------------
__device__ __forceinline__ uint32_t smem_u32(const void* p) {
    uint32_t a;
    asm("{ .reg .u64 t; cvta.to.shared.u64 t, %1; cvt.u32.u64 %0, t; }" : "=r"(a) : "l"(p));
    return a;
}
__device__ __forceinline__ void mma16816h(float* d, const uint32_t* a, const uint32_t* b) {
    asm volatile("mma.sync.aligned.m16n8k16.row.col.f32.f16.f16.f32 "
                 "{%0,%1,%2,%3}, {%4,%5,%6,%7}, {%8,%9}, {%0,%1,%2,%3};"
                 : "+f"(d[0]), "+f"(d[1]), "+f"(d[2]), "+f"(d[3])
                 : "r"(a[0]), "r"(a[1]), "r"(a[2]), "r"(a[3]), "r"(b[0]), "r"(b[1]));
}
__device__ __forceinline__ void ldsm4(uint32_t* r, uint32_t addr) {
    asm volatile("ldmatrix.sync.aligned.m8n8.x4.shared.b16 {%0,%1,%2,%3}, [%4];"
                 : "=r"(r[0]), "=r"(r[1]), "=r"(r[2]), "=r"(r[3]) : "r"(addr));
}
#define CP16(dst, src) asm volatile("cp.async.cg.shared.global [%0], [%1], 16;" :: "r"(dst), "l"(src))
#define CP_COMMIT()    asm volatile("cp.async.commit_group;" ::: "memory")
#define CP_WAIT1()     asm volatile("cp.async.wait_group 1;" ::: "memory")
#define CP_WAIT0()     asm volatile("cp.async.wait_group 0;" ::: "memory")

// ---------------- fp16 store helpers ----------------
__device__ __forceinline__ void store4h(__half* p, float4 v) {
    __half2 h01 = __floats2half2_rn(v.x, v.y);
    __half2 h23 = __floats2half2_rn(v.z, v.w);
    uint2 u;
    u.x = *(unsigned*)&h01; u.y = *(unsigned*)&h23;
    *(uint2*)p = u;
}
__device__ __forceinline__ void store2h(__half* p, float2 v) {
    __half2 h = __floats2half2_rn(v.x, v.y);
    *(unsigned*)p = *(unsigned*)&h;
}

// ---------------- prep: weight packing (fp16 hi/lo) + row marking + cnt reset ----
__global__ void prep(const float* __restrict__ Ws0, const float* __restrict__ Wn0,
                     const float* __restrict__ Ws1, const float* __restrict__ Wn1,
                     const float* __restrict__ Wp1, const float* __restrict__ Wp2,
                     const int* __restrict__ nidx1) {
    int b = blockIdx.x, t = threadIdx.x;
    if (b == 0 && t == 0) g_cnt = 0;
    if (b < HID) {
        int n = b, k = t;   // 256 x 256 transpose + split
        auto split1 = [](float v, __half* h, __half* l) {
            __half hh = __float2half_rn(v);
            *h = hh; *l = __float2half_rn(v - __half2float(hh));
        };
        float w0 = (k < IN_DIM) ? Ws0[k * HID + n] : Wn0[(k - IN_DIM) * HID + n];
        split1(w0, &g_W0h[n * HID + k], &g_W0l[n * HID + k]);
        split1(Wp1[k * HID + n], &g_P1h[n * HID + k], &g_P1l[n * HID + k]);
        split1(Wp2[k * HID + n], &g_P2h[n * HID + k], &g_P2l[n * HID + k]);
        split1(Ws1[k * HID + n], &g_W1h[n * 2 * HID + k],       &g_W1l[n * 2 * HID + k]);
        split1(Wn1[k * HID + n], &g_W1h[n * 2 * HID + k + HID], &g_W1l[n * 2 * HID + k + HID]);
    } else {
        int e = (b - HID) * 256 + t;    // 480 blocks cover N2n*FAN
        g_flags[nidx1[e]] = 1;
    }
}

// ---------------- compaction (warp-aggregated atomics) ----------------
__global__ void compact_rows() {
    int i = blockIdx.x * blockDim.x + threadIdx.x;          // 480 x 256
    int lane = threadIdx.x & 31;
    int f = (i < N2n) || g_flags[i];
    unsigned m = __ballot_sync(0xffffffffu, f);
    int base = 0;
    if (lane == 0 && m) base = atomicAdd(&g_cnt, __popc(m));
    base = __shfl_sync(0xffffffffu, base, 0);
    if (f) {
        int p = base + __popc(m & ((1u << lane) - 1u));
        g_orig[p] = i;
        g_newid[i] = p;
    }
}

// ---------------- layer0 gather + mean -> fp16 (compacted rows only) ----------------
__global__ void __launch_bounds__(256, 6) gather_agg0(
    const float* __restrict__ nf, const int* __restrict__ gids,
    const int* __restrict__ nidx) {
    int gw   = (blockIdx.x * blockDim.x + threadIdx.x) >> 5;
    int lane = threadIdx.x & 31;
    if (gw >= __ldg(&g_cnt)) return;
    int row = __ldg(&g_orig[gw]);

    int idx_l = 0;
    if (lane < FAN)       idx_l = gids[nidx[(size_t)row * FAN + lane]];
    else if (lane == FAN) idx_l = gids[row];

    int gs = __shfl_sync(0xffffffffu, idx_l, FAN);
    float4 s = __ldg((const float4*)nf + (size_t)gs * (IN_DIM / 4) + lane);

    float4 aa = make_float4(0.f, 0.f, 0.f, 0.f), ab = aa;
    #pragma unroll
    for (int k = 0; k < FAN; k += 2) {
        int ga = __shfl_sync(0xffffffffu, idx_l, k);
        int gb = __shfl_sync(0xffffffffu, idx_l, k + 1);
        float4 va = __ldg((const float4*)nf + (size_t)ga * (IN_DIM / 4) + lane);
        float4 vb = __ldg((const float4*)nf + (size_t)gb * (IN_DIM / 4) + lane);
        aa.x += va.x; aa.y += va.y; aa.z += va.z; aa.w += va.w;
        ab.x += vb.x; ab.y += vb.y; ab.z += vb.z; ab.w += vb.w;
    }
    const float inv = 1.0f / FAN;
    float4 a = make_float4((aa.x + ab.x) * inv, (aa.y + ab.y) * inv,
                           (aa.z + ab.z) * inv, (aa.w + ab.w) * inv);

    size_t rb = (size_t)gw * HID;
    store4h(g_u0 + rb + 4 * lane,       s);
    store4h(g_u0 + rb + 128 + 4 * lane, a);
}

// ---------------- layer1 gather + mean over compacted g_h0 -> fp16 ----------------
__global__ void gather_agg1(const int* __restrict__ nidx) {
    int gw   = (blockIdx.x * blockDim.x + threadIdx.x) >> 5;
    int lane = threadIdx.x & 31;

    int idx_l = 0;
    if (lane < FAN)       idx_l = __ldg(&g_newid[nidx[(size_t)gw * FAN + lane]]);
    else if (lane == FAN) idx_l = __ldg(&g_newid[gw]);

    float4 a0 = make_float4(0.f, 0.f, 0.f, 0.f), a1 = a0;
    #pragma unroll
    for (int k = 0; k < FAN; k++) {
        int j = __shfl_sync(0xffffffffu, idx_l, k);
        const float4* row = (const float4*)g_h0 + (size_t)j * (HID / 4);
        float4 v0 = __ldg(row + lane);
        float4 v1 = __ldg(row + 32 + lane);
        a0.x += v0.x; a0.y += v0.y; a0.z += v0.z; a0.w += v0.w;
        a1.x += v1.x; a1.y += v1.y; a1.z += v1.z; a1.w += v1.w;
    }
    int js = __shfl_sync(0xffffffffu, idx_l, FAN);
    const float4* srow = (const float4*)g_h0 + (size_t)js * (HID / 4);
    float4 s0 = __ldg(srow + lane), s1 = __ldg(srow + 32 + lane);

    const float inv = 1.0f / FAN;
    a0.x *= inv; a0.y *= inv; a0.z *= inv; a0.w *= inv;
    a1.x *= inv; a1.y *= inv; a1.z *= inv; a1.w *= inv;

    size_t rb = (size_t)gw * (2 * HID);
    store4h(g_u1 + rb + 4 * lane,       s0);
    store4h(g_u1 + rb + 128 + 4 * lane, s1);
    store4h(g_u1 + rb + 256 + 4 * lane, a0);
    store4h(g_u1 + rb + 384 + 4 * lane, a1);
}

// ---------------- HMMA GEMM: C[M,256] = act(A[M,K] @ W[K,256] + bias) ----------------
// A single fp16 [M,K] row-major (activations exact to fp16 round, 2^-12);
// W as transposed fp16 hi/lo Wt[256,K] (22-bit). 2-pass: D = A*Wh + A*Wl.
// BM=128, BN=128, BK=32; 256 threads = 8 warps (2m x 4n), warp tile 64x32.
// smem: 2 stages x (A 8K | Bh 8K | Bl 8K) = 48 KB dynamic; 2 CTAs/SM.
constexpr int GEMM_SMEM = 49152;

template <bool RELU, bool HOUT>
__global__ void __launch_bounds__(256, 2) hgemm(
    const __half* __restrict__ A,
    const __half* __restrict__ Bh, const __half* __restrict__ Bl,
    const float* __restrict__ bias,
    float* __restrict__ Cf, __half* __restrict__ Ch,
    int K, const int* Mlim)
{
    extern __shared__ char sm[];
    const int bm = blockIdx.y * 128, bn = blockIdx.x * 128;
    if (Mlim != nullptr && bm >= __ldg(Mlim)) return;
    const uint32_t sb = smem_u32(sm);
    const int tid = threadIdx.x, lane = tid & 31, wid = tid >> 5;
    const int wm = (wid >> 2) * 64, wn = (wid & 3) * 32;
    const int nCh = K >> 5;

    auto swo = [](int r, int c) -> uint32_t { return (uint32_t)(r * 64 + ((c ^ ((r >> 1) & 3)) << 4)); };

    auto load_stage = [&](int stage, int kc) {
        const uint32_t base = sb + stage * 24576;
        #pragma unroll
        for (int i = 0; i < 6; i++) {
            int q = tid + i * 256;              // 1536 16B chunks per stage
            int part = q >> 9;                  // 0=A, 1=Bh, 2=Bl
            int w = q & 511;
            int r = w >> 2, c = w & 3;
            uint32_t so = swo(r, c) + (uint32_t)part * 8192;
            const __half* src;
            if (part == 0)      src = A  + (size_t)(bm + r) * K + kc * 32 + c * 8;
            else if (part == 1) src = Bh + (size_t)(bn + r) * K + kc * 32 + c * 8;
            else                src = Bl + (size_t)(bn + r) * K + kc * 32 + c * 8;
            CP16(base + so, src);
        }
    };

    float acc[4][4][4];
    #pragma unroll
    for (int i = 0; i < 4; i++)
        #pragma unroll
        for (int j = 0; j < 4; j++)
            #pragma unroll
            for (int k = 0; k < 4; k++) acc[i][j][k] = 0.f;

    load_stage(0, 0);
    CP_COMMIT();

    for (int kc = 0; kc < nCh; kc++) {
        if (kc + 1 < nCh) { load_stage((kc + 1) & 1, kc + 1); CP_COMMIT(); CP_WAIT1(); }
        else              { CP_WAIT0(); }
        __syncthreads();

        const uint32_t base = sb + (kc & 1) * 24576;
        #pragma unroll
        for (int ks = 0; ks < 2; ks++) {
            uint32_t aR[4][4], bH[2][4], bL[2][4];
            const int akch = 2 * ks + (lane >> 4);
            const int arow = wm + (lane & 15);
            #pragma unroll
            for (int p = 0; p < 2; p++) {
                int row = wn + p * 16 + (lane & 7) + ((lane >> 4) << 3);
                int kch = 2 * ks + ((lane >> 3) & 1);
                uint32_t so = swo(row, kch);
                ldsm4(bH[p], base + 8192  + so);
                ldsm4(bL[p], base + 16384 + so);
            }
            #pragma unroll
            for (int mt = 0; mt < 4; mt++)
                ldsm4(aR[mt], base + swo(arow + mt * 16, akch));
            // pass 1: A * Wh  (16 independent mma)
            #pragma unroll
            for (int mt = 0; mt < 4; mt++)
                #pragma unroll
                for (int nt = 0; nt < 4; nt++)
                    mma16816h(acc[mt][nt], aR[mt], &bH[nt >> 1][(nt & 1) * 2]);
            // pass 2: A * Wl
            #pragma unroll
            for (int mt = 0; mt < 4; mt++)
                #pragma unroll
                for (int nt = 0; nt < 4; nt++)
                    mma16816h(acc[mt][nt], aR[mt], &bL[nt >> 1][(nt & 1) * 2]);
        }
        __syncthreads();
    }

    // epilogue: bias + act; float2 or half2 stores
    const int tg = lane >> 2, tt = lane & 3;
    #pragma unroll
    for (int nt = 0; nt < 4; nt++) {
        int col = bn + wn + nt * 8 + 2 * tt;
        float2 b2 = *(const float2*)(bias + col);
        #pragma unroll
        for (int mt = 0; mt < 4; mt++) {
            int r0 = bm + wm + mt * 16 + tg;
            float2 v0, v1;
            v0.x = acc[mt][nt][0] + b2.x; v0.y = acc[mt][nt][1] + b2.y;
            v1.x = acc[mt][nt][2] + b2.x; v1.y = acc[mt][nt][3] + b2.y;
            if (RELU) {
                v0.x = fmaxf(v0.x, 0.f); v0.y = fmaxf(v0.y, 0.f);
                v1.x = fmaxf(v1.x, 0.f); v1.y = fmaxf(v1.y, 0.f);
            }
            size_t o0 = (size_t)r0 * 256 + col, o1 = o0 + 8 * 256;
            if (!HOUT) {
                *(float2*)(Cf + o0) = v0;
                *(float2*)(Cf + o1) = v1;
            } else {
                store2h(Ch + o0, v0);
                store2h(Ch + o1, v1);
            }
        }
    }
}

// ---------------- z[r] = h2[r mod B] * h2[B + r] -> fp16 ----------------
__global__ void build_z() {
    int r = blockIdx.x, c = threadIdx.x;   // grid 8192, block 64
    const float4* s = (const float4*)(g_h2 + (size_t)(r & (Bsz - 1)) * HID);
    const float4* o = (const float4*)(g_h2 + (size_t)(Bsz + r) * HID);
    float4 a = s[c], b = o[c];
    float4 v = make_float4(a.x * b.x, a.y * b.y, a.z * b.z, a.w * b.w);
    store4h(g_zq + (size_t)r * HID + 4 * c, v);
}

// ---------------- scores = z2 @ Wp3 + bp3 ----------------
__global__ void final_dot(const float* __restrict__ Wp3, const float* __restrict__ bp3,
                          float* __restrict__ out) {
    int gw   = (blockIdx.x * blockDim.x + threadIdx.x) >> 5;
    int lane = threadIdx.x & 31;
    const float4* z = (const float4*)(g_z2 + (size_t)gw * HID);
    const float4* w = (const float4*)Wp3;
    float4 z0 = z[lane], z1 = z[32 + lane];
    float4 w0 = __ldg(w + lane), w1 = __ldg(w + 32 + lane);
    float s = z0.x * w0.x + z0.y * w0.y + z0.z * w0.z + z0.w * w0.w
            + z1.x * w1.x + z1.y * w1.y + z1.z * w1.z + z1.w * w1.w;
    #pragma unroll
    for (int o = 16; o; o >>= 1) s += __shfl_xor_sync(0xffffffffu, s, o);
    if (lane == 0) out[gw] = s + bp3[0];
}

extern "C" void kernel_launch(void* const* d_in, const int* in_sizes, int n_in,
                              void* d_out, int out_size) {
    const float* node_feat = (const float*)d_in[0];
    const int*   gids0     = (const int*)d_in[1];
    const int*   nidx0     = (const int*)d_in[2];
    const int*   nidx1     = (const int*)d_in[3];
    const float* Ws0 = (const float*)d_in[4];
    const float* Wn0 = (const float*)d_in[5];
    const float* b0  = (const float*)d_in[6];
    const float* Ws1 = (const float*)d_in[7];
    const float* Wn1 = (const float*)d_in[8];
    const float* b1  = (const float*)d_in[9];
    const float* Wp1 = (const float*)d_in[10];
    const float* bp1 = (const float*)d_in[11];
    const float* Wp2 = (const float*)d_in[12];
    const float* bp2 = (const float*)d_in[13];
    const float* Wp3 = (const float*)d_in[14];
    const float* bp3 = (const float*)d_in[15];
    float* out = (float*)d_out;

    cudaFuncSetAttribute(hgemm<true,  false>, cudaFuncAttributeMaxDynamicSharedMemorySize, GEMM_SMEM);
    cudaFuncSetAttribute(hgemm<false, false>, cudaFuncAttributeMaxDynamicSharedMemorySize, GEMM_SMEM);
    cudaFuncSetAttribute(hgemm<true,  true >, cudaFuncAttributeMaxDynamicSharedMemorySize, GEMM_SMEM);

    __half *u0, *u1, *zq, *z1q;
    __half *W0h, *W0l, *W1h, *W1l, *P1h, *P1l, *P2h, *P2l;
    float *h0, *h2, *z2;
    int* cnt;
    cudaGetSymbolAddress((void**)&u0,  g_u0);  cudaGetSymbolAddress((void**)&u1,  g_u1);
    cudaGetSymbolAddress((void**)&zq,  g_zq);  cudaGetSymbolAddress((void**)&z1q, g_z1q);
    cudaGetSymbolAddress((void**)&W0h, g_W0h); cudaGetSymbolAddress((void**)&W0l, g_W0l);
    cudaGetSymbolAddress((void**)&W1h, g_W1h); cudaGetSymbolAddress((void**)&W1l, g_W1l);
    cudaGetSymbolAddress((void**)&P1h, g_P1h); cudaGetSymbolAddress((void**)&P1l, g_P1l);
    cudaGetSymbolAddress((void**)&P2h, g_P2h); cudaGetSymbolAddress((void**)&P2l, g_P2l);
    cudaGetSymbolAddress((void**)&h0,  g_h0);  cudaGetSymbolAddress((void**)&h2,  g_h2);
    cudaGetSymbolAddress((void**)&z2,  g_z2);  cudaGetSymbolAddress((void**)&cnt, g_cnt);

    // (1) pack weights (fp16 hi/lo) + mark live rows + reset counter
    prep<<<HID + (N2n * FAN) / 256, 256>>>(Ws0, Wn0, Ws1, Wn1, Wp1, Wp2, nidx1);
    // (2) compact live rows
    compact_rows<<<N1n / 256, 256>>>();
    // (3) layer 0 gather (compacted rows only, fp16 out)
    gather_agg0<<<N1n / 8, 256>>>(node_feat, gids0, nidx0);
    // (4) layer 0 GEMM — profiled launch
    hgemm<true, false><<<dim3(2, N1n / 128), 256, GEMM_SMEM>>>(
        u0, W0h, W0l, b0, h0, nullptr, 2 * IN_DIM, cnt);

    // layer 1
    gather_agg1<<<N2n / 8, 256>>>(nidx1);
    hgemm<false, false><<<dim3(2, N2n / 128), 256, GEMM_SMEM>>>(
        u1, W1h, W1l, b1, h2, nullptr, 2 * HID, nullptr);

    // edge MLP
    build_z<<<ZROWS, 64>>>();
    hgemm<true, true><<<dim3(2, ZROWS / 128), 256, GEMM_SMEM>>>(
        zq, P1h, P1l, bp1, nullptr, z1q, HID, nullptr);
    hgemm<true, false><<<dim3(2, ZROWS / 128), 256, GEMM_SMEM>>>(
        z1q, P2h, P2l, bp2, z2, nullptr, HID, nullptr);
    final_dot<<<ZROWS / 8, 256>>>(Wp3, bp3, out);
}

// round 16
// speedup vs baseline: 1.6472x; 1.0603x over previous
#include <cuda_runtime.h>
#include <cuda_fp16.h>
#include <cstdint>

#define FAN 10
constexpr int IN_DIM = 128;
constexpr int HID    = 256;
constexpr int Bsz    = 4096;
constexpr int N2n    = 3 * Bsz;       // 12288
constexpr int N1n    = N2n * FAN;     // 122880
constexpr int ZROWS  = 2 * Bsz;       // 8192

// ---------------- scratch (device globals: allocation-free) ----------------
__device__ __align__(16) __half g_u0 [(size_t)N1n * HID];        // layer0 GEMM input (fp16)
__device__ __align__(16) __half g_h0 [(size_t)N1n * HID];        // layer0 output (fp16!)
__device__ __align__(16) __half g_u1 [(size_t)N2n * 2 * HID];
__device__ __align__(16) float  g_h2 [(size_t)N2n * HID];
__device__ __align__(16) __half g_zq [(size_t)ZROWS * HID];
__device__ __align__(16) __half g_z1q[(size_t)ZROWS * HID];
__device__ __align__(16) float  g_z2 [(size_t)ZROWS * HID];
// transposed fp16 hi/lo weights: [N=256, K]
__device__ __align__(16) __half g_W0h[HID * HID],     g_W0l[HID * HID];
__device__ __align__(16) __half g_W1h[HID * 2 * HID], g_W1l[HID * 2 * HID];
__device__ __align__(16) __half g_P1h[HID * HID],     g_P1l[HID * HID];
__device__ __align__(16) __half g_P2h[HID * HID],     g_P2l[HID * HID];
// row compaction (g_flags zero-init BSS; marks idempotent with fixed inputs)
__device__ int g_cnt;
__device__ int g_flags[N1n];
__device__ int g_newid[N1n];
__device__ int g_orig [N1n];

// ---------------- PTX helpers ----------------
__device__ __forceinline__ uint32_t smem_u32(const void* p) {
    uint32_t a;
    asm("{ .reg .u64 t; cvta.to.shared.u64 t, %1; cvt.u32.u64 %0, t; }" : "=r"(a) : "l"(p));
    return a;
}
__device__ __forceinline__ void mma16816h(float* d, const uint32_t* a, const uint32_t* b) {
    asm volatile("mma.sync.aligned.m16n8k16.row.col.f32.f16.f16.f32 "
                 "{%0,%1,%2,%3}, {%4,%5,%6,%7}, {%8,%9}, {%0,%1,%2,%3};"
                 : "+f"(d[0]), "+f"(d[1]), "+f"(d[2]), "+f"(d[3])
                 : "r"(a[0]), "r"(a[1]), "r"(a[2]), "r"(a[3]), "r"(b[0]), "r"(b[1]));
}
__device__ __forceinline__ void ldsm4(uint32_t* r, uint32_t addr) {
    asm volatile("ldmatrix.sync.aligned.m8n8.x4.shared.b16 {%0,%1,%2,%3}, [%4];"
                 : "=r"(r[0]), "=r"(r[1]), "=r"(r[2]), "=r"(r[3]) : "r"(addr));
}
#define CP16(dst, src) asm volatile("cp.async.cg.shared.global [%0], [%1], 16;" :: "r"(dst), "l"(src))
#define CP_COMMIT()    asm volatile("cp.async.commit_group;" ::: "memory")
#define CP_WAIT0()     asm volatile("cp.async.wait_group 0;" ::: "memory")

// ---------------- fp16 store helpers ----------------
__device__ __forceinline__ void store4h(__half* p, float4 v) {
    __half2 h01 = __floats2half2_rn(v.x, v.y);
    __half2 h23 = __floats2half2_rn(v.z, v.w);
    uint2 u;
    u.x = *(unsigned*)&h01; u.y = *(unsigned*)&h23;
    *(uint2*)p = u;
}
__device__ __forceinline__ void store2h(__half* p, float2 v) {
    __half2 h = __floats2half2_rn(v.x, v.y);
    *(unsigned*)p = *(unsigned*)&h;
}

// ---------------- prep: weight packing (fp16 hi/lo) + row marking + cnt reset ----
__global__ void prep(const float* __restrict__ Ws0, const float* __restrict__ Wn0,
                     const float* __restrict__ Ws1, const float* __restrict__ Wn1,
                     const float* __restrict__ Wp1, const float* __restrict__ Wp2,
                     const int* __restrict__ nidx1) {
    int b = blockIdx.x, t = threadIdx.x;
    if (b == 0 && t == 0) g_cnt = 0;
    if (b < HID) {
        int n = b, k = t;   // 256 x 256 transpose + split
        auto split1 = [](float v, __half* h, __half* l) {
            __half hh = __float2half_rn(v);
            *h = hh; *l = __float2half_rn(v - __half2float(hh));
        };
        float w0 = (k < IN_DIM) ? Ws0[k * HID + n] : Wn0[(k - IN_DIM) * HID + n];
        split1(w0, &g_W0h[n * HID + k], &g_W0l[n * HID + k]);
        split1(Wp1[k * HID + n], &g_P1h[n * HID + k], &g_P1l[n * HID + k]);
        split1(Wp2[k * HID + n], &g_P2h[n * HID + k], &g_P2l[n * HID + k]);
        split1(Ws1[k * HID + n], &g_W1h[n * 2 * HID + k],       &g_W1l[n * 2 * HID + k]);
        split1(Wn1[k * HID + n], &g_W1h[n * 2 * HID + k + HID], &g_W1l[n * 2 * HID + k + HID]);
    } else {
        int e = (b - HID) * 256 + t;    // 480 blocks cover N2n*FAN
        g_flags[nidx1[e]] = 1;
    }
}

// ---------------- compaction (warp-aggregated atomics) ----------------
__global__ void compact_rows() {
    int i = blockIdx.x * blockDim.x + threadIdx.x;          // 480 x 256
    int lane = threadIdx.x & 31;
    int f = (i < N2n) || g_flags[i];
    unsigned m = __ballot_sync(0xffffffffu, f);
    int base = 0;
    if (lane == 0 && m) base = atomicAdd(&g_cnt, __popc(m));
    base = __shfl_sync(0xffffffffu, base, 0);
    if (f) {
        int p = base + __popc(m & ((1u << lane) - 1u));
        g_orig[p] = i;
        g_newid[i] = p;
    }
}

// ---------------- layer0 gather + mean -> fp16 (compacted rows only) ----------------
__global__ void __launch_bounds__(256, 6) gather_agg0(
    const float* __restrict__ nf, const int* __restrict__ gids,
    const int* __restrict__ nidx) {
    int gw   = (blockIdx.x * blockDim.x + threadIdx.x) >> 5;
    int lane = threadIdx.x & 31;
    if (gw >= __ldg(&g_cnt)) return;
    int row = __ldg(&g_orig[gw]);

    int idx_l = 0;
    if (lane < FAN)       idx_l = gids[nidx[(size_t)row * FAN + lane]];
    else if (lane == FAN) idx_l = gids[row];

    int gs = __shfl_sync(0xffffffffu, idx_l, FAN);
    float4 s = __ldg((const float4*)nf + (size_t)gs * (IN_DIM / 4) + lane);

    float4 aa = make_float4(0.f, 0.f, 0.f, 0.f), ab = aa;
    #pragma unroll
    for (int k = 0; k < FAN; k += 2) {
        int ga = __shfl_sync(0xffffffffu, idx_l, k);
        int gb = __shfl_sync(0xffffffffu, idx_l, k + 1);
        float4 va = __ldg((const float4*)nf + (size_t)ga * (IN_DIM / 4) + lane);
        float4 vb = __ldg((const float4*)nf + (size_t)gb * (IN_DIM / 4) + lane);
        aa.x += va.x; aa.y += va.y; aa.z += va.z; aa.w += va.w;
        ab.x += vb.x; ab.y += vb.y; ab.z += vb.z; ab.w += vb.w;
    }
    const float inv = 1.0f / FAN;
    float4 a = make_float4((aa.x + ab.x) * inv, (aa.y + ab.y) * inv,
                           (aa.z + ab.z) * inv, (aa.w + ab.w) * inv);

    size_t rb = (size_t)gw * HID;
    store4h(g_u0 + rb + 4 * lane,       s);
    store4h(g_u0 + rb + 128 + 4 * lane, a);
}

// ---------------- layer1 gather + mean over fp16 g_h0 -> fp16 u1 ----------------
// h0 row = 256 halves = 512B = 32 uint4; lane owns cols 8*lane..8*lane+7.
__global__ void gather_agg1(const int* __restrict__ nidx) {
    int gw   = (blockIdx.x * blockDim.x + threadIdx.x) >> 5;
    int lane = threadIdx.x & 31;

    int idx_l = 0;
    if (lane < FAN)       idx_l = __ldg(&g_newid[nidx[(size_t)gw * FAN + lane]]);
    else if (lane == FAN) idx_l = __ldg(&g_newid[gw]);

    const uint4* h0p = (const uint4*)g_h0;
    float acc[8];
    #pragma unroll
    for (int i = 0; i < 8; i++) acc[i] = 0.f;

    #pragma unroll
    for (int k = 0; k < FAN; k++) {
        int j = __shfl_sync(0xffffffffu, idx_l, k);
        uint4 v = __ldg(h0p + (size_t)j * 32 + lane);
        const __half2* hv = (const __half2*)&v;
        #pragma unroll
        for (int i = 0; i < 4; i++) {
            float2 f = __half22float2(hv[i]);
            acc[2 * i]     += f.x;
            acc[2 * i + 1] += f.y;
        }
    }
    int js = __shfl_sync(0xffffffffu, idx_l, FAN);
    uint4 s = __ldg(h0p + (size_t)js * 32 + lane);

    const float inv = 1.0f / FAN;
    uint4 av;
    __half2* ah = (__half2*)&av;
    #pragma unroll
    for (int i = 0; i < 4; i++)
        ah[i] = __floats2half2_rn(acc[2 * i] * inv, acc[2 * i + 1] * inv);

    uint4* u1 = (uint4*)(g_u1 + (size_t)gw * (2 * HID));
    u1[lane]      = s;    // self: bit-exact copy of h0 row
    u1[32 + lane] = av;   // agg
}

// ---------------- HMMA GEMM: C[M,256] = act(A[M,K] @ W[K,256] + bias) ----------------
// A single fp16 [M,K]; W transposed fp16 hi/lo Wt[256,K]. 2-pass: D = A*Wh + A*Wl.
// BM=128, BN=64, BK=32; 256 threads = 8 warps (4m x 2n), warp tile 32x32.
// 3 CTAs/SM (acc 32 regs -> ~76 total). One __syncthreads per k-chunk.
// smem: 2 stages x (A 8K | Bh 4K | Bl 4K) = 32 KB dynamic.
constexpr int GEMM_SMEM = 32768;

template <bool RELU, bool HOUT>
__global__ void __launch_bounds__(256, 3) hgemm(
    const __half* __restrict__ A,
    const __half* __restrict__ Bh, const __half* __restrict__ Bl,
    const float* __restrict__ bias,
    float* __restrict__ Cf, __half* __restrict__ Ch,
    int K, const int* Mlim)
{
    extern __shared__ char sm[];
    const int bm = blockIdx.y * 128, bn = blockIdx.x * 64;
    if (Mlim != nullptr && bm >= __ldg(Mlim)) return;
    const uint32_t sb = smem_u32(sm);
    const int tid = threadIdx.x, lane = tid & 31, wid = tid >> 5;
    const int wm = (wid >> 1) * 32, wn = (wid & 1) * 32;
    const int nCh = K >> 5;

    auto swo = [](int r, int c) -> uint32_t { return (uint32_t)(r * 64 + ((c ^ ((r >> 1) & 3)) << 4)); };

    auto load_stage = [&](int stage, int kc) {
        const uint32_t base = sb + stage * 16384;
        #pragma unroll
        for (int i = 0; i < 4; i++) {
            int q = tid + i * 256;              // 1024 16B chunks per stage
            uint32_t dst; const __half* src;
            if (q < 512) {                      // A: 128 rows x 4 chunks
                int r = q >> 2, c = q & 3;
                dst = base + swo(r, c);
                src = A + (size_t)(bm + r) * K + kc * 32 + c * 8;
            } else if (q < 768) {               // Bh: 64 rows x 4 chunks
                int w = q - 512, r = w >> 2, c = w & 3;
                dst = base + 8192 + swo(r, c);
                src = Bh + (size_t)(bn + r) * K + kc * 32 + c * 8;
            } else {                            // Bl
                int w = q - 768, r = w >> 2, c = w & 3;
                dst = base + 12288 + swo(r, c);
                src = Bl + (size_t)(bn + r) * K + kc * 32 + c * 8;
            }
            CP16(dst, src);
        }
    };

    float acc[2][4][4];
    #pragma unroll
    for (int i = 0; i < 2; i++)
        #pragma unroll
        for (int j = 0; j < 4; j++)
            #pragma unroll
            for (int k = 0; k < 4; k++) acc[i][j][k] = 0.f;

    load_stage(0, 0);
    CP_COMMIT();

    for (int kc = 0; kc < nCh; kc++) {
        CP_WAIT0();
        __syncthreads();        // stage kc visible; all warps done reading stage kc-1
        if (kc + 1 < nCh) { load_stage((kc + 1) & 1, kc + 1); CP_COMMIT(); }

        const uint32_t base = sb + (kc & 1) * 16384;
        #pragma unroll
        for (int ks = 0; ks < 2; ks++) {
            uint32_t aR[2][4], bH[2][4], bL[2][4];
            const int akch = 2 * ks + (lane >> 4);
            const int arow = wm + (lane & 15);
            #pragma unroll
            for (int p = 0; p < 2; p++) {
                int row = wn + p * 16 + (lane & 7) + ((lane >> 4) << 3);
                int kch = 2 * ks + ((lane >> 3) & 1);
                uint32_t so = swo(row, kch);
                ldsm4(bH[p], base + 8192  + so);
                ldsm4(bL[p], base + 12288 + so);
            }
            #pragma unroll
            for (int mt = 0; mt < 2; mt++)
                ldsm4(aR[mt], base + swo(arow + mt * 16, akch));
            // pass 1: A * Wh (8 independent mma)
            #pragma unroll
            for (int mt = 0; mt < 2; mt++)
                #pragma unroll
                for (int nt = 0; nt < 4; nt++)
                    mma16816h(acc[mt][nt], aR[mt], &bH[nt >> 1][(nt & 1) * 2]);
            // pass 2: A * Wl
            #pragma unroll
            for (int mt = 0; mt < 2; mt++)
                #pragma unroll
                for (int nt = 0; nt < 4; nt++)
                    mma16816h(acc[mt][nt], aR[mt], &bL[nt >> 1][(nt & 1) * 2]);
        }
        __syncthreads();        // all warps done with stage kc before it is reloaded
    }

    // epilogue: bias + act; float2 or half2 stores
    const int tg = lane >> 2, tt = lane & 3;
    #pragma unroll
    for (int nt = 0; nt < 4; nt++) {
        int col = bn + wn + nt * 8 + 2 * tt;
        float2 b2 = *(const float2*)(bias + col);
        #pragma unroll
        for (int mt = 0; mt < 2; mt++) {
            int r0 = bm + wm + mt * 16 + tg;
            float2 v0, v1;
            v0.x = acc[mt][nt][0] + b2.x; v0.y = acc[mt][nt][1] + b2.y;
            v1.x = acc[mt][nt][2] + b2.x; v1.y = acc[mt][nt][3] + b2.y;
            if (RELU) {
                v0.x = fmaxf(v0.x, 0.f); v0.y = fmaxf(v0.y, 0.f);
                v1.x = fmaxf(v1.x, 0.f); v1.y = fmaxf(v1.y, 0.f);
            }
            size_t o0 = (size_t)r0 * 256 + col, o1 = o0 + 8 * 256;
            if (!HOUT) {
                *(float2*)(Cf + o0) = v0;
                *(float2*)(Cf + o1) = v1;
            } else {
                store2h(Ch + o0, v0);
                store2h(Ch + o1, v1);
            }
        }
    }
}

// ---------------- z[r] = h2[r mod B] * h2[B + r] -> fp16 ----------------
__global__ void build_z() {
    int r = blockIdx.x, c = threadIdx.x;   // grid 8192, block 64
    const float4* s = (const float4*)(g_h2 + (size_t)(r & (Bsz - 1)) * HID);
    const float4* o = (const float4*)(g_h2 + (size_t)(Bsz + r) * HID);
    float4 a = s[c], b = o[c];
    float4 v = make_float4(a.x * b.x, a.y * b.y, a.z * b.z, a.w * b.w);
    store4h(g_zq + (size_t)r * HID + 4 * c, v);
}

// ---------------- scores = z2 @ Wp3 + bp3 ----------------
__global__ void final_dot(const float* __restrict__ Wp3, const float* __restrict__ bp3,
                          float* __restrict__ out) {
    int gw   = (blockIdx.x * blockDim.x + threadIdx.x) >> 5;
    int lane = threadIdx.x & 31;
    const float4* z = (const float4*)(g_z2 + (size_t)gw * HID);
    const float4* w = (const float4*)Wp3;
    float4 z0 = z[lane], z1 = z[32 + lane];
    float4 w0 = __ldg(w + lane), w1 = __ldg(w + 32 + lane);
    float s = z0.x * w0.x + z0.y * w0.y + z0.z * w0.z + z0.w * w0.w
            + z1.x * w1.x + z1.y * w1.y + z1.z * w1.z + z1.w * w1.w;
    #pragma unroll
    for (int o = 16; o; o >>= 1) s += __shfl_xor_sync(0xffffffffu, s, o);
    if (lane == 0) out[gw] = s + bp3[0];
}

extern "C" void kernel_launch(void* const* d_in, const int* in_sizes, int n_in,
                              void* d_out, int out_size) {
    const float* node_feat = (const float*)d_in[0];
    const int*   gids0     = (const int*)d_in[1];
    const int*   nidx0     = (const int*)d_in[2];
    const int*   nidx1     = (const int*)d_in[3];
    const float* Ws0 = (const float*)d_in[4];
    const float* Wn0 = (const float*)d_in[5];
    const float* b0  = (const float*)d_in[6];
    const float* Ws1 = (const float*)d_in[7];
    const float* Wn1 = (const float*)d_in[8];
    const float* b1  = (const float*)d_in[9];
    const float* Wp1 = (const float*)d_in[10];
    const float* bp1 = (const float*)d_in[11];
    const float* Wp2 = (const float*)d_in[12];
    const float* bp2 = (const float*)d_in[13];
    const float* Wp3 = (const float*)d_in[14];
    const float* bp3 = (const float*)d_in[15];
    float* out = (float*)d_out;

    cudaFuncSetAttribute(hgemm<true,  false>, cudaFuncAttributeMaxDynamicSharedMemorySize, GEMM_SMEM);
    cudaFuncSetAttribute(hgemm<false, false>, cudaFuncAttributeMaxDynamicSharedMemorySize, GEMM_SMEM);
    cudaFuncSetAttribute(hgemm<true,  true >, cudaFuncAttributeMaxDynamicSharedMemorySize, GEMM_SMEM);

    __half *u0, *u1, *h0, *zq, *z1q;
    __half *W0h, *W0l, *W1h, *W1l, *P1h, *P1l, *P2h, *P2l;
    float *h2, *z2;
    int* cnt;
    cudaGetSymbolAddress((void**)&u0,  g_u0);  cudaGetSymbolAddress((void**)&u1,  g_u1);
    cudaGetSymbolAddress((void**)&h0,  g_h0);
    cudaGetSymbolAddress((void**)&zq,  g_zq);  cudaGetSymbolAddress((void**)&z1q, g_z1q);
    cudaGetSymbolAddress((void**)&W0h, g_W0h); cudaGetSymbolAddress((void**)&W0l, g_W0l);
    cudaGetSymbolAddress((void**)&W1h, g_W1h); cudaGetSymbolAddress((void**)&W1l, g_W1l);
    cudaGetSymbolAddress((void**)&P1h, g_P1h); cudaGetSymbolAddress((void**)&P1l, g_P1l);
    cudaGetSymbolAddress((void**)&P2h, g_P2h); cudaGetSymbolAddress((void**)&P2l, g_P2l);
    cudaGetSymbolAddress((void**)&h2,  g_h2);
    cudaGetSymbolAddress((void**)&z2,  g_z2);  cudaGetSymbolAddress((void**)&cnt, g_cnt);

    // (1) pack weights (fp16 hi/lo) + mark live rows + reset counter
    prep<<<HID + (N2n * FAN) / 256, 256>>>(Ws0, Wn0, Ws1, Wn1, Wp1, Wp2, nidx1);
    // (2) compact live rows
    compact_rows<<<N1n / 256, 256>>>();
    // (3) layer 0 gather (compacted rows only, fp16 out)
    gather_agg0<<<N1n / 8, 256>>>(node_feat, gids0, nidx0);
    // (4) layer 0 GEMM — profiled launch; fp16 h0 output
    hgemm<true, true><<<dim3(4, N1n / 128), 256, GEMM_SMEM>>>(
        u0, W0h, W0l, b0, nullptr, h0, 2 * IN_DIM, cnt);

    // layer 1
    gather_agg1<<<N2n / 8, 256>>>(nidx1);
    hgemm<false, false><<<dim3(4, N2n / 128), 256, GEMM_SMEM>>>(
        u1, W1h, W1l, b1, h2, nullptr, 2 * HID, nullptr);

    // edge MLP
    build_z<<<ZROWS, 64>>>();
    hgemm<true, true><<<dim3(4, ZROWS / 128), 256, GEMM_SMEM>>>(
        zq, P1h, P1l, bp1, nullptr, z1q, HID, nullptr);
    hgemm<true, false><<<dim3(4, ZROWS / 128), 256, GEMM_SMEM>>>(
        z1q, P2h, P2l, bp2, z2, nullptr, HID, nullptr);
    final_dot<<<ZROWS / 8, 256>>>(Wp3, bp3, out);
}